// round 3
// baseline (speedup 1.0000x reference)
#include <cuda_runtime.h>
#include <cuda_bf16.h>
#include <math.h>

// Problem constants (fixed by the dataset)
#define NSEQ 4096
#define DIM  768
#define NH   8
#define HD   96
#define TD   2304
#define MAXB 2
#define SCALE 0.036084391824351615f   // 768^-0.5

// Scratch: [3][B*NH][NSEQ][HD]
__device__ float g_qkv[3ull * MAXB * NH * NSEQ * HD];

// ---------------- packed f32x2 helpers (sm_103a FFMA2) ----------------
__device__ __forceinline__ double ffma2(double a, double b, double c) {
    double d; asm("fma.rn.f32x2 %0, %1, %2, %3;" : "=d"(d) : "d"(a), "d"(b), "d"(c)); return d;
}
__device__ __forceinline__ double fmul2(double a, double b) {
    double d; asm("mul.rn.f32x2 %0, %1, %2;" : "=d"(d) : "d"(a), "d"(b)); return d;
}
__device__ __forceinline__ double pack2(float x) {
    double d; asm("mov.b64 %0, {%1, %1};" : "=d"(d) : "f"(x)); return d;
}
__device__ __forceinline__ float lo2(double d) { return __int_as_float(__double2loint(d)); }
__device__ __forceinline__ float hi2(double d) { return __int_as_float(__double2hiint(d)); }

// ---------------------------------------------------------------------------
// Kernel 1: QKV GEMM.  C[8192,2304] = X[8192,768] @ W[768,2304] + bias,
// scattered into g_qkv as [s][b*NH+h][n][d].
// 64x64 tile, 256 threads, 4x4 per-thread tile done as 4x(2 packed pairs),
// k-tile 32.  A stored DUPLICATED in smem so packed broadcast pairs come
// straight out of LDS.128.
// ---------------------------------------------------------------------------
#define GKT 32
__global__ __launch_bounds__(256) void qkv_gemm_kernel(
    const float* __restrict__ X, const float* __restrict__ W,
    const float* __restrict__ bias, int B)
{
    __shared__ float As[GKT][128];   // As[kk][2r+e] duplicated A rows
    __shared__ float Ws[GKT][64];    // Ws[kk][c]

    const int tid = threadIdx.x;
    const int tx = tid & 15;
    const int ty = tid >> 4;
    const int row0 = blockIdx.y * 64;
    const int col0 = blockIdx.x * 64;

    const int fr = tid & 63;     // fill row/col
    const int kb = tid >> 6;     // 0..3  -> kk = kb*8 .. kb*8+7

    double acc[4][2];
#pragma unroll
    for (int i = 0; i < 4; i++) { acc[i][0] = 0.0; acc[i][1] = 0.0; }

    for (int k0 = 0; k0 < DIM; k0 += GKT) {
        // A fill: each thread reads 8 consecutive k of one row, writes duplicated
        {
            const float* src = &X[(size_t)(row0 + fr) * DIM + k0 + kb * 8];
            float4 a0 = *(const float4*)&src[0];
            float4 a1 = *(const float4*)&src[4];
            const int kk = kb * 8;
            *(float2*)&As[kk + 0][2 * fr] = make_float2(a0.x, a0.x);
            *(float2*)&As[kk + 1][2 * fr] = make_float2(a0.y, a0.y);
            *(float2*)&As[kk + 2][2 * fr] = make_float2(a0.z, a0.z);
            *(float2*)&As[kk + 3][2 * fr] = make_float2(a0.w, a0.w);
            *(float2*)&As[kk + 4][2 * fr] = make_float2(a1.x, a1.x);
            *(float2*)&As[kk + 5][2 * fr] = make_float2(a1.y, a1.y);
            *(float2*)&As[kk + 6][2 * fr] = make_float2(a1.z, a1.z);
            *(float2*)&As[kk + 7][2 * fr] = make_float2(a1.w, a1.w);
        }
        // W fill: 8 k-rows, coalesced
#pragma unroll
        for (int j = 0; j < 8; j++)
            Ws[kb * 8 + j][fr] = W[(size_t)(k0 + kb * 8 + j) * TD + col0 + fr];
        __syncthreads();

#pragma unroll
        for (int kk = 0; kk < GKT; kk++) {
            double2 aq0 = *(const double2*)&As[kk][8 * ty];      // (a0,a0),(a1,a1)
            double2 aq1 = *(const double2*)&As[kk][8 * ty + 4];  // (a2,a2),(a3,a3)
            double2 wq  = *(const double2*)&Ws[kk][4 * tx];      // (w0,w1),(w2,w3)
            acc[0][0] = ffma2(aq0.x, wq.x, acc[0][0]);
            acc[0][1] = ffma2(aq0.x, wq.y, acc[0][1]);
            acc[1][0] = ffma2(aq0.y, wq.x, acc[1][0]);
            acc[1][1] = ffma2(aq0.y, wq.y, acc[1][1]);
            acc[2][0] = ffma2(aq1.x, wq.x, acc[2][0]);
            acc[2][1] = ffma2(aq1.x, wq.y, acc[2][1]);
            acc[3][0] = ffma2(aq1.y, wq.x, acc[3][0]);
            acc[3][1] = ffma2(aq1.y, wq.y, acc[3][1]);
        }
        __syncthreads();
    }

    // bias + scatter into g_qkv[s][b*NH+h][n][d]
    const size_t per_s = (size_t)B * NH * NSEQ * HD;
#pragma unroll
    for (int i = 0; i < 4; i++) {
        const int r = row0 + ty * 4 + i;
        const int b = r >> 12;
        const int n = r & 4095;
        float av[4] = { lo2(acc[i][0]), hi2(acc[i][0]), lo2(acc[i][1]), hi2(acc[i][1]) };
#pragma unroll
        for (int j = 0; j < 4; j++) {
            const int c = col0 + tx * 4 + j;
            const float v = av[j] + bias[c];
            const int s = c / DIM;
            const int rem = c - s * DIM;
            const int h = rem / HD;
            const int d = rem - h * HD;
            g_qkv[(size_t)s * per_s +
                  (((size_t)(b * NH + h)) * NSEQ + n) * HD + d] = v;
        }
    }
}

// ---------------------------------------------------------------------------
// Kernel 2: flash attention, fp32, packed f32x2.
// grid = (NSEQ/128, B*NH), 512 threads, 128 q-rows x 64 k-cols per tile.
// smem: Qd (Q duplicated, transposed)  96 x 256
//       Kt (K transposed)              96 x 64
//       Vs (V row-major, padded)       64 x 100
//       Sd (P duplicated)             128 x 132
// ---------------------------------------------------------------------------
#define QD_STR 256
#define KT_STR 64
#define VS_STR 100
#define SD_STR 132
#define ATTN_SMEM_FLOATS (96*QD_STR + 96*KT_STR + 64*VS_STR + 128*SD_STR)
#define ATTN_SMEM_BYTES  (ATTN_SMEM_FLOATS * 4)

__global__ __launch_bounds__(512, 1) void attn_kernel(
    float* __restrict__ out, int B)
{
    extern __shared__ float smem[];
    float* Qd = smem;                      // 96*256
    float* Kt = Qd + 96 * QD_STR;          // 96*64
    float* Vs = Kt + 96 * KT_STR;          // 64*100
    float* Sd = Vs + 64 * VS_STR;          // 128*132

    const int tid = threadIdx.x;
    const int tx = tid & 15;               // 0..15 : 4 S-cols / 6 O-cols
    const int ty = tid >> 4;               // 0..31 : 4 rows
    const int bh = blockIdx.y;
    const int q0 = blockIdx.x * 128;

    const size_t per_s = (size_t)B * NH * NSEQ * HD;
    const float* Qg = g_qkv + (size_t)bh * NSEQ * HD;
    const float* Kg = Qg + per_s;
    const float* Vg = Kg + per_s;

    // ---- load Q tile once, duplicated + transposed ----
    {
        const int r  = tid & 127;
        const int db = tid >> 7;           // 0..3, each covers 24 d
        const float* src = &Qg[(size_t)(q0 + r) * HD + db * 24];
#pragma unroll
        for (int c = 0; c < 6; c++) {
            float4 v = *(const float4*)&src[c * 4];
            const int d = db * 24 + c * 4;
            *(float2*)&Qd[(d + 0) * QD_STR + 2 * r] = make_float2(v.x, v.x);
            *(float2*)&Qd[(d + 1) * QD_STR + 2 * r] = make_float2(v.y, v.y);
            *(float2*)&Qd[(d + 2) * QD_STR + 2 * r] = make_float2(v.z, v.z);
            *(float2*)&Qd[(d + 3) * QD_STR + 2 * r] = make_float2(v.w, v.w);
        }
    }

    float mrow[4], lrow[4];
    double Ov[4][3];
#pragma unroll
    for (int i = 0; i < 4; i++) {
        mrow[i] = -INFINITY; lrow[i] = 0.f;
        Ov[i][0] = 0.0; Ov[i][1] = 0.0; Ov[i][2] = 0.0;
    }

    const int kr  = tid & 63;              // K/V fill row
    const int kdb = tid >> 6;              // 0..7, each covers 12 d

    for (int kt = 0; kt < NSEQ; kt += 64) {
        // ---- fill K (transposed) and V (row-major) ----
        {
            const float* ks = &Kg[(size_t)(kt + kr) * HD + kdb * 12];
            const float* vs = &Vg[(size_t)(kt + kr) * HD + kdb * 12];
#pragma unroll
            for (int c = 0; c < 3; c++) {
                float4 v = *(const float4*)&ks[c * 4];
                const int d = kdb * 12 + c * 4;
                Kt[(d + 0) * KT_STR + kr] = v.x;
                Kt[(d + 1) * KT_STR + kr] = v.y;
                Kt[(d + 2) * KT_STR + kr] = v.z;
                Kt[(d + 3) * KT_STR + kr] = v.w;
            }
#pragma unroll
            for (int c = 0; c < 3; c++)
                *(float4*)&Vs[kr * VS_STR + kdb * 12 + c * 4] = *(const float4*)&vs[c * 4];
        }
        __syncthreads();

        // ---- phase 1: S = Q K^T  (4 rows x 2 packed col-pairs) ----
        double sp[4][2];
#pragma unroll
        for (int i = 0; i < 4; i++) { sp[i][0] = 0.0; sp[i][1] = 0.0; }
        const float* qb = &Qd[8 * ty];
        const float* kb = &Kt[4 * tx];
#pragma unroll 8
        for (int d = 0; d < HD; d++) {
            double2 aq0 = *(const double2*)&qb[d * QD_STR];      // (a0,a0),(a1,a1)
            double2 aq1 = *(const double2*)&qb[d * QD_STR + 4];  // (a2,a2),(a3,a3)
            double2 kq  = *(const double2*)&kb[d * KT_STR];      // (k0,k1),(k2,k3)
            sp[0][0] = ffma2(aq0.x, kq.x, sp[0][0]);
            sp[0][1] = ffma2(aq0.x, kq.y, sp[0][1]);
            sp[1][0] = ffma2(aq0.y, kq.x, sp[1][0]);
            sp[1][1] = ffma2(aq0.y, kq.y, sp[1][1]);
            sp[2][0] = ffma2(aq1.x, kq.x, sp[2][0]);
            sp[2][1] = ffma2(aq1.x, kq.y, sp[2][1]);
            sp[3][0] = ffma2(aq1.y, kq.x, sp[3][0]);
            sp[3][1] = ffma2(aq1.y, kq.y, sp[3][1]);
        }

        // ---- online softmax (per row; 16-lane tx reduction) + store P dup'd ----
#pragma unroll
        for (int i = 0; i < 4; i++) {
            float s0 = lo2(sp[i][0]) * SCALE, s1 = hi2(sp[i][0]) * SCALE;
            float s2 = lo2(sp[i][1]) * SCALE, s3 = hi2(sp[i][1]) * SCALE;
            float tmax = fmaxf(fmaxf(s0, s1), fmaxf(s2, s3));
#pragma unroll
            for (int msk = 8; msk >= 1; msk >>= 1)
                tmax = fmaxf(tmax, __shfl_xor_sync(0xffffffffu, tmax, msk));
            const float mnew = fmaxf(mrow[i], tmax);
            s0 = __expf(s0 - mnew); s1 = __expf(s1 - mnew);
            s2 = __expf(s2 - mnew); s3 = __expf(s3 - mnew);
            float tsum = (s0 + s1) + (s2 + s3);
#pragma unroll
            for (int msk = 8; msk >= 1; msk >>= 1)
                tsum += __shfl_xor_sync(0xffffffffu, tsum, msk);
            const float corr = __expf(mrow[i] - mnew);
            lrow[i] = lrow[i] * corr + tsum;
            mrow[i] = mnew;
            const double cp = pack2(corr);
            Ov[i][0] = fmul2(Ov[i][0], cp);
            Ov[i][1] = fmul2(Ov[i][1], cp);
            Ov[i][2] = fmul2(Ov[i][2], cp);
            double2 st0; st0.x = pack2(s0); st0.y = pack2(s1);
            double2 st1; st1.x = pack2(s2); st1.y = pack2(s3);
            *(double2*)&Sd[(4 * ty + i) * SD_STR + 8 * tx]     = st0;
            *(double2*)&Sd[(4 * ty + i) * SD_STR + 8 * tx + 4] = st1;
        }
        __syncwarp();   // P produced & consumed within the same half-warp

        // ---- phase 2: O += P @ V  (4 rows x 3 packed col-pairs, 2 k per iter) ----
        const float* sdb = &Sd[(4 * ty) * SD_STR];
        const float* vvb = &Vs[6 * tx];
#pragma unroll 4
        for (int kp = 0; kp < 64; kp += 2) {
            double2 p0 = *(const double2*)&sdb[0 * SD_STR + 2 * kp];
            double2 p1 = *(const double2*)&sdb[1 * SD_STR + 2 * kp];
            double2 p2 = *(const double2*)&sdb[2 * SD_STR + 2 * kp];
            double2 p3 = *(const double2*)&sdb[3 * SD_STR + 2 * kp];
            double va0 = *(const double*)&vvb[(kp + 0) * VS_STR + 0];
            double va1 = *(const double*)&vvb[(kp + 0) * VS_STR + 2];
            double va2 = *(const double*)&vvb[(kp + 0) * VS_STR + 4];
            double vb0 = *(const double*)&vvb[(kp + 1) * VS_STR + 0];
            double vb1 = *(const double*)&vvb[(kp + 1) * VS_STR + 2];
            double vb2 = *(const double*)&vvb[(kp + 1) * VS_STR + 4];
            Ov[0][0] = ffma2(p0.x, va0, Ov[0][0]);
            Ov[0][1] = ffma2(p0.x, va1, Ov[0][1]);
            Ov[0][2] = ffma2(p0.x, va2, Ov[0][2]);
            Ov[1][0] = ffma2(p1.x, va0, Ov[1][0]);
            Ov[1][1] = ffma2(p1.x, va1, Ov[1][1]);
            Ov[1][2] = ffma2(p1.x, va2, Ov[1][2]);
            Ov[2][0] = ffma2(p2.x, va0, Ov[2][0]);
            Ov[2][1] = ffma2(p2.x, va1, Ov[2][1]);
            Ov[2][2] = ffma2(p2.x, va2, Ov[2][2]);
            Ov[3][0] = ffma2(p3.x, va0, Ov[3][0]);
            Ov[3][1] = ffma2(p3.x, va1, Ov[3][1]);
            Ov[3][2] = ffma2(p3.x, va2, Ov[3][2]);
            Ov[0][0] = ffma2(p0.y, vb0, Ov[0][0]);
            Ov[0][1] = ffma2(p0.y, vb1, Ov[0][1]);
            Ov[0][2] = ffma2(p0.y, vb2, Ov[0][2]);
            Ov[1][0] = ffma2(p1.y, vb0, Ov[1][0]);
            Ov[1][1] = ffma2(p1.y, vb1, Ov[1][1]);
            Ov[1][2] = ffma2(p1.y, vb2, Ov[1][2]);
            Ov[2][0] = ffma2(p2.y, vb0, Ov[2][0]);
            Ov[2][1] = ffma2(p2.y, vb1, Ov[2][1]);
            Ov[2][2] = ffma2(p2.y, vb2, Ov[2][2]);
            Ov[3][0] = ffma2(p3.y, vb0, Ov[3][0]);
            Ov[3][1] = ffma2(p3.y, vb1, Ov[3][1]);
            Ov[3][2] = ffma2(p3.y, vb2, Ov[3][2]);
        }
        __syncthreads();   // before next K/V fill
    }

    // ---- epilogue: normalize, packed stores ----
    const int b = bh / NH;
    const int h = bh - b * NH;
#pragma unroll
    for (int i = 0; i < 4; i++) {
        const double invp = pack2(1.f / lrow[i]);
        const int n = q0 + 4 * ty + i;
        float* orow = out + ((size_t)b * NSEQ + n) * DIM + h * HD + 6 * tx;
        *(double*)&orow[0] = fmul2(Ov[i][0], invp);
        *(double*)&orow[2] = fmul2(Ov[i][1], invp);
        *(double*)&orow[4] = fmul2(Ov[i][2], invp);
    }
}

// ---------------------------------------------------------------------------
extern "C" void kernel_launch(void* const* d_in, const int* in_sizes, int n_in,
                              void* d_out, int out_size)
{
    const float* x    = (const float*)d_in[0];   // (B, N, 768)
    const float* Wqkv = (const float*)d_in[1];   // (768, 2304)
    const float* bqkv = (const float*)d_in[2];   // (2304,)
    float* out = (float*)d_out;

    const int B = in_sizes[0] / (NSEQ * DIM);

    // QKV projection + scatter
    {
        dim3 grid(TD / 64, (B * NSEQ) / 64);
        qkv_gemm_kernel<<<grid, 256>>>(x, Wqkv, bqkv, B);
    }

    // flash attention
    {
        cudaFuncSetAttribute(attn_kernel,
                             cudaFuncAttributeMaxDynamicSharedMemorySize,
                             ATTN_SMEM_BYTES);
        dim3 grid(NSEQ / 128, B * NH);
        attn_kernel<<<grid, 512, ATTN_SMEM_BYTES>>>(out, B);
    }
}

// round 4
// speedup vs baseline: 2.9514x; 2.9514x over previous
#include <cuda_runtime.h>
#include <cuda_bf16.h>
#include <math.h>

// Problem constants (fixed by the dataset)
#define NSEQ 4096
#define DIM  768
#define NH   8
#define HD   96
#define TD   2304
#define MAXB 2
#define SCALE 0.036084391824351615f   // 768^-0.5

// Scratch: [3][B*NH][NSEQ][HD]
__device__ float g_qkv[3ull * MAXB * NH * NSEQ * HD];

// ---------------- helpers ----------------
__device__ __forceinline__ unsigned tf32u(float x) {
    unsigned y; asm("cvt.rna.tf32.f32 %0, %1;" : "=r"(y) : "f"(x)); return y;
}
// D += A(16x8,row,tf32) * B(8x8,col,tf32), fp32 accum
__device__ __forceinline__ void mma8(float* c, const unsigned* a, unsigned b0, unsigned b1) {
    asm volatile(
        "mma.sync.aligned.m16n8k8.row.col.f32.tf32.tf32.f32 "
        "{%0,%1,%2,%3}, {%4,%5,%6,%7}, {%8,%9}, {%0,%1,%2,%3};"
        : "+f"(c[0]), "+f"(c[1]), "+f"(c[2]), "+f"(c[3])
        : "r"(a[0]), "r"(a[1]), "r"(a[2]), "r"(a[3]), "r"(b0), "r"(b1));
}

// ---------------------------------------------------------------------------
// Kernel 1: QKV GEMM (TF32 mma).  C[8192,2304] = X @ W + bias -> scatter.
// CTA 256 thr (8 warps), tile 128x128, k-step 32. Warp tile 32x64.
// ---------------------------------------------------------------------------
#define XS_STR 36     // == 4 (mod 32): conflict-free A-frag loads
#define WS_STR 136    // == 8 (mod 32): conflict-free B-frag loads

__global__ __launch_bounds__(256) void qkv_gemm_kernel(
    const float* __restrict__ X, const float* __restrict__ W,
    const float* __restrict__ bias, int B)
{
    __shared__ unsigned Xs[128 * XS_STR];   // 18.4 KB (tf32 bits)
    __shared__ unsigned Ws[32 * WS_STR];    // 17.4 KB

    const int tid  = threadIdx.x;
    const int lane = tid & 31;
    const int gid  = lane >> 2;
    const int tig  = lane & 3;
    const int w    = tid >> 5;
    const int wm   = w >> 1;               // 0..3
    const int wn   = w & 1;                // 0..1
    const int row0 = blockIdx.y * 128;
    const int col0 = blockIdx.x * 128;

    float c[2][8][4];
#pragma unroll
    for (int mt = 0; mt < 2; mt++)
#pragma unroll
        for (int nt = 0; nt < 8; nt++)
#pragma unroll
            for (int j = 0; j < 4; j++) c[mt][nt][j] = 0.f;

    const int xr = tid >> 1, xk = (tid & 1) * 16;   // X fill: row, k-slice
    const int wr = tid >> 3, wc = (tid & 7) * 16;   // W fill: k-row, col-slice

    for (int k0 = 0; k0 < DIM; k0 += 32) {
        // fill X tile (tf32-rounded)
        {
            const float* src = X + (size_t)(row0 + xr) * DIM + k0 + xk;
#pragma unroll
            for (int i = 0; i < 4; i++) {
                float4 v = *(const float4*)(src + 4 * i);
                uint4 u = make_uint4(tf32u(v.x), tf32u(v.y), tf32u(v.z), tf32u(v.w));
                *(uint4*)&Xs[xr * XS_STR + xk + 4 * i] = u;
            }
        }
        // fill W tile (tf32-rounded)
        {
            const float* src = W + (size_t)(k0 + wr) * TD + col0 + wc;
#pragma unroll
            for (int i = 0; i < 4; i++) {
                float4 v = *(const float4*)(src + 4 * i);
                uint4 u = make_uint4(tf32u(v.x), tf32u(v.y), tf32u(v.z), tf32u(v.w));
                *(uint4*)&Ws[wr * WS_STR + wc + 4 * i] = u;
            }
        }
        __syncthreads();

#pragma unroll
        for (int kc = 0; kc < 4; kc++) {
            unsigned a[2][4];
#pragma unroll
            for (int mt = 0; mt < 2; mt++) {
                const unsigned* qp = &Xs[(wm * 32 + mt * 16 + gid) * XS_STR + kc * 8 + tig];
                a[mt][0] = qp[0];
                a[mt][2] = qp[4];
                a[mt][1] = qp[8 * XS_STR];
                a[mt][3] = qp[8 * XS_STR + 4];
            }
#pragma unroll
            for (int nt = 0; nt < 8; nt++) {
                unsigned b0 = Ws[(kc * 8 + tig)     * WS_STR + wn * 64 + nt * 8 + gid];
                unsigned b1 = Ws[(kc * 8 + tig + 4) * WS_STR + wn * 64 + nt * 8 + gid];
                mma8(c[0][nt], a[0], b0, b1);
                mma8(c[1][nt], a[1], b0, b1);
            }
        }
        __syncthreads();
    }

    // epilogue: bias + scatter into g_qkv[s][b*NH+h][n][d]
    const size_t per_s = (size_t)B * NH * NSEQ * HD;
#pragma unroll
    for (int mt = 0; mt < 2; mt++) {
        const int r_lo = row0 + wm * 32 + mt * 16 + gid;
        const int r_hi = r_lo + 8;
#pragma unroll
        for (int nt = 0; nt < 8; nt++) {
            const int cA = col0 + wn * 64 + nt * 8 + 2 * tig;
#pragma unroll
            for (int e = 0; e < 2; e++) {
                const int cc = cA + e;
                const float bb = __ldg(&bias[cc]);
                const int s  = cc / DIM;
                const int rem = cc - s * DIM;
                const int h  = rem / HD;
                const int d  = rem - h * HD;
#pragma unroll
                for (int half = 0; half < 2; half++) {
                    const int r = half ? r_hi : r_lo;
                    const int b = r >> 12;
                    const int n = r & 4095;
                    const float v = c[mt][nt][half * 2 + e] + bb;
                    g_qkv[(size_t)s * per_s +
                          (((size_t)(b * NH + h)) * NSEQ + n) * HD + d] = v;
                }
            }
        }
    }
}

// ---------------------------------------------------------------------------
// Kernel 2: flash attention with TF32 mma.
// grid = (NSEQ/128, B*NH), CTA 256 thr (8 warps), q-tile 128 (16 rows/warp),
// kv-tile 64.  P converted C-frag -> A-frag in registers via shuffles.
// smem: Qs[128][100] + Ks[64][100] + Vs[64][104]  (tf32 bits) = 103.4 KB
// ---------------------------------------------------------------------------
#define QS_STR 100
#define KS_STR 100
#define VS_STR 104
#define ATTN_SMEM_BYTES ((128 * QS_STR + 64 * KS_STR + 64 * VS_STR) * 4)

__global__ __launch_bounds__(256, 2) void attn_kernel(
    float* __restrict__ out, int B)
{
    extern __shared__ unsigned asmem[];
    unsigned* Qs = asmem;                       // 128*100
    unsigned* Ks = Qs + 128 * QS_STR;           // 64*100
    unsigned* Vs = Ks + 64 * KS_STR;            // 64*104

    const int tid  = threadIdx.x;
    const int lane = tid & 31;
    const int gid  = lane >> 2;
    const int tig  = lane & 3;
    const int w    = tid >> 5;                  // 0..7, warp owns rows [16w,16w+16)
    const int bh   = blockIdx.y;
    const int q0   = blockIdx.x * 128;

    const size_t per_s = (size_t)B * NH * NSEQ * HD;
    const float* Qg = g_qkv + (size_t)bh * NSEQ * HD;
    const float* Kg = Qg + per_s;
    const float* Vg = Kg + per_s;

    // ---- load Q tile once (tf32-rounded) ----
    {
        const int row = tid >> 1, dp = (tid & 1) * 48;
        const float* src = Qg + (size_t)(q0 + row) * HD + dp;
#pragma unroll
        for (int i = 0; i < 12; i++) {
            float4 v = *(const float4*)(src + 4 * i);
            uint4 u = make_uint4(tf32u(v.x), tf32u(v.y), tf32u(v.z), tf32u(v.w));
            *(uint4*)&Qs[row * QS_STR + dp + 4 * i] = u;
        }
    }

    // softmax state + O accumulators (12 d-tiles x 4)
    float m_lo = -INFINITY, m_hi = -INFINITY, l_lo = 0.f, l_hi = 0.f;
    float o[12][4];
#pragma unroll
    for (int nt = 0; nt < 12; nt++)
#pragma unroll
        for (int j = 0; j < 4; j++) o[nt][j] = 0.f;

    // shuffle source lanes for C->A fragment conversion
    const int srcA = (lane & 28) | (tig >> 1);
    const int srcB = srcA + 2;
    const bool oddl = lane & 1;

    const int fkv = (tid & 127) >> 1;           // K/V fill row
    const int fdp = (tid & 1) * 48;
    const int farr = tid >> 7;                  // 0: K, 1: V (warp-uniform)

    for (int kt = 0; kt < NSEQ; kt += 64) {
        __syncthreads();   // previous tile fully consumed
        // ---- fill K/V tiles (tf32-rounded) ----
        {
            const float* src = (farr ? Vg : Kg) + (size_t)(kt + fkv) * HD + fdp;
            unsigned* dst = farr ? &Vs[fkv * VS_STR + fdp] : &Ks[fkv * KS_STR + fdp];
#pragma unroll
            for (int i = 0; i < 12; i++) {
                float4 v = *(const float4*)(src + 4 * i);
                uint4 u = make_uint4(tf32u(v.x), tf32u(v.y), tf32u(v.z), tf32u(v.w));
                *(uint4*)&dst[4 * i] = u;
            }
        }
        __syncthreads();

        // ---- S = Q K^T : 12 k-chunks x 8 n-tiles ----
        float s[8][4];
#pragma unroll
        for (int nt = 0; nt < 8; nt++)
#pragma unroll
            for (int j = 0; j < 4; j++) s[nt][j] = 0.f;

        const unsigned* qbase = &Qs[(w * 16 + gid) * QS_STR + tig];
#pragma unroll
        for (int kc = 0; kc < 12; kc++) {
            unsigned a[4];
            a[0] = qbase[kc * 8];
            a[2] = qbase[kc * 8 + 4];
            a[1] = qbase[8 * QS_STR + kc * 8];
            a[3] = qbase[8 * QS_STR + kc * 8 + 4];
#pragma unroll
            for (int nt = 0; nt < 8; nt++) {
                const unsigned* kp = &Ks[(nt * 8 + gid) * KS_STR + kc * 8 + tig];
                mma8(s[nt], a, kp[0], kp[4]);
            }
        }

        // ---- online softmax ----
        float rmax_lo = -INFINITY, rmax_hi = -INFINITY;
#pragma unroll
        for (int nt = 0; nt < 8; nt++) {
            rmax_lo = fmaxf(rmax_lo, fmaxf(s[nt][0], s[nt][1]));
            rmax_hi = fmaxf(rmax_hi, fmaxf(s[nt][2], s[nt][3]));
        }
        rmax_lo = fmaxf(rmax_lo, __shfl_xor_sync(0xffffffffu, rmax_lo, 1));
        rmax_lo = fmaxf(rmax_lo, __shfl_xor_sync(0xffffffffu, rmax_lo, 2));
        rmax_hi = fmaxf(rmax_hi, __shfl_xor_sync(0xffffffffu, rmax_hi, 1));
        rmax_hi = fmaxf(rmax_hi, __shfl_xor_sync(0xffffffffu, rmax_hi, 2));

        const float mn_lo = fmaxf(m_lo, rmax_lo * SCALE);
        const float mn_hi = fmaxf(m_hi, rmax_hi * SCALE);
        const float corr_lo = __expf(m_lo - mn_lo);
        const float corr_hi = __expf(m_hi - mn_hi);
        m_lo = mn_lo; m_hi = mn_hi;

        float sum_lo = 0.f, sum_hi = 0.f;
#pragma unroll
        for (int nt = 0; nt < 8; nt++) {
            float e0 = __expf(fmaf(s[nt][0], SCALE, -mn_lo));
            float e1 = __expf(fmaf(s[nt][1], SCALE, -mn_lo));
            float e2 = __expf(fmaf(s[nt][2], SCALE, -mn_hi));
            float e3 = __expf(fmaf(s[nt][3], SCALE, -mn_hi));
            sum_lo += e0 + e1;
            sum_hi += e2 + e3;
            s[nt][0] = __uint_as_float(tf32u(e0));
            s[nt][1] = __uint_as_float(tf32u(e1));
            s[nt][2] = __uint_as_float(tf32u(e2));
            s[nt][3] = __uint_as_float(tf32u(e3));
        }
        sum_lo += __shfl_xor_sync(0xffffffffu, sum_lo, 1);
        sum_lo += __shfl_xor_sync(0xffffffffu, sum_lo, 2);
        sum_hi += __shfl_xor_sync(0xffffffffu, sum_hi, 1);
        sum_hi += __shfl_xor_sync(0xffffffffu, sum_hi, 2);
        l_lo = l_lo * corr_lo + sum_lo;
        l_hi = l_hi * corr_hi + sum_hi;

#pragma unroll
        for (int nt = 0; nt < 12; nt++) {
            o[nt][0] *= corr_lo; o[nt][1] *= corr_lo;
            o[nt][2] *= corr_hi; o[nt][3] *= corr_hi;
        }

        // ---- O += P @ V : 8 k-chunks x 12 d-tiles ----
#pragma unroll
        for (int kc = 0; kc < 8; kc++) {
            // C-frag (s[kc]) -> A-frag via shuffles
            float p0 = s[kc][0], p1 = s[kc][1], p2 = s[kc][2], p3 = s[kc][3];
            float t0 = __shfl_sync(0xffffffffu, p0, srcA);
            float t1 = __shfl_sync(0xffffffffu, p1, srcA);
            float t2 = __shfl_sync(0xffffffffu, p2, srcA);
            float t3 = __shfl_sync(0xffffffffu, p3, srcA);
            float u0 = __shfl_sync(0xffffffffu, p0, srcB);
            float u1 = __shfl_sync(0xffffffffu, p1, srcB);
            float u2 = __shfl_sync(0xffffffffu, p2, srcB);
            float u3 = __shfl_sync(0xffffffffu, p3, srcB);
            unsigned a[4];
            a[0] = __float_as_uint(oddl ? t1 : t0);
            a[1] = __float_as_uint(oddl ? t3 : t2);
            a[2] = __float_as_uint(oddl ? u1 : u0);
            a[3] = __float_as_uint(oddl ? u3 : u2);
#pragma unroll
            for (int nt = 0; nt < 12; nt++) {
                const unsigned* vp = &Vs[(kc * 8 + tig) * VS_STR + nt * 8 + gid];
                mma8(o[nt], a, vp[0], vp[4 * VS_STR]);
            }
        }
    }

    // ---- epilogue ----
    const int b = bh >> 3;
    const int h = bh & 7;
    const int r_lo = q0 + w * 16 + gid;
    const int r_hi = r_lo + 8;
    const float inv_lo = 1.f / l_lo;
    const float inv_hi = 1.f / l_hi;
    float* out_lo = out + ((size_t)b * NSEQ + r_lo) * DIM + h * HD;
    float* out_hi = out + ((size_t)b * NSEQ + r_hi) * DIM + h * HD;
#pragma unroll
    for (int nt = 0; nt < 12; nt++) {
        const int d = nt * 8 + 2 * tig;
        *(float2*)&out_lo[d] = make_float2(o[nt][0] * inv_lo, o[nt][1] * inv_lo);
        *(float2*)&out_hi[d] = make_float2(o[nt][2] * inv_hi, o[nt][3] * inv_hi);
    }
}

// ---------------------------------------------------------------------------
extern "C" void kernel_launch(void* const* d_in, const int* in_sizes, int n_in,
                              void* d_out, int out_size)
{
    const float* x    = (const float*)d_in[0];   // (B, N, 768)
    const float* Wqkv = (const float*)d_in[1];   // (768, 2304)
    const float* bqkv = (const float*)d_in[2];   // (2304,)
    float* out = (float*)d_out;

    const int B = in_sizes[0] / (NSEQ * DIM);

    // QKV projection + scatter
    {
        dim3 grid(TD / 128, (B * NSEQ) / 128);
        qkv_gemm_kernel<<<grid, 256>>>(x, Wqkv, bqkv, B);
    }

    // flash attention
    {
        cudaFuncSetAttribute(attn_kernel,
                             cudaFuncAttributeMaxDynamicSharedMemorySize,
                             ATTN_SMEM_BYTES);
        dim3 grid(NSEQ / 128, B * NH);
        attn_kernel<<<grid, 256, ATTN_SMEM_BYTES>>>(out, B);
    }
}

// round 7
// speedup vs baseline: 4.8099x; 1.6297x over previous
#include <cuda_runtime.h>
#include <cuda_bf16.h>
#include <math.h>

// Problem constants (fixed by the dataset)
#define NSEQ 4096
#define DIM  768
#define NH   8
#define HD   96
#define TD   2304
#define MAXB 2
#define SCALE 0.036084391824351615f   // 768^-0.5

// Scratch: [3][B*NH][NSEQ][HD]
__device__ float g_qkv[3ull * MAXB * NH * NSEQ * HD];

// ---------------- helpers ----------------
__device__ __forceinline__ unsigned tf32u(float x) {
    unsigned y; asm("cvt.rna.tf32.f32 %0, %1;" : "=r"(y) : "f"(x)); return y;
}
// D += A(16x8,row,tf32) * B(8x8,col,tf32), fp32 accum
__device__ __forceinline__ void mma8(float* c, const unsigned* a, unsigned b0, unsigned b1) {
    asm volatile(
        "mma.sync.aligned.m16n8k8.row.col.f32.tf32.tf32.f32 "
        "{%0,%1,%2,%3}, {%4,%5,%6,%7}, {%8,%9}, {%0,%1,%2,%3};"
        : "+f"(c[0]), "+f"(c[1]), "+f"(c[2]), "+f"(c[3])
        : "r"(a[0]), "r"(a[1]), "r"(a[2]), "r"(a[3]), "r"(b0), "r"(b1));
}
__device__ __forceinline__ void cp16(unsigned dst, const void* src) {
    asm volatile("cp.async.cg.shared.global [%0], [%1], 16;" :: "r"(dst), "l"(src));
}
__device__ __forceinline__ void cp_commit() {
    asm volatile("cp.async.commit_group;" ::: "memory");
}
__device__ __forceinline__ void cp_wait0() {
    asm volatile("cp.async.wait_group 0;" ::: "memory");
}

// ---------------------------------------------------------------------------
// Kernel 1: QKV GEMM (TF32 mma).  C[8192,2304] = X @ W + bias -> scatter.
// CTA 256 thr (8 warps), tile 128x128, k-step 32, register double buffering.
// ---------------------------------------------------------------------------
#define XS_STR 36     // == 4 (mod 32): conflict-free A-frag loads
#define WS_STR 136    // == 8 (mod 32): conflict-free B-frag loads

__global__ __launch_bounds__(256, 2) void qkv_gemm_kernel(
    const float* __restrict__ X, const float* __restrict__ W,
    const float* __restrict__ bias, int B)
{
    __shared__ unsigned Xs[128 * XS_STR];
    __shared__ unsigned Ws[32 * WS_STR];

    const int tid  = threadIdx.x;
    const int lane = tid & 31;
    const int gid  = lane >> 2;
    const int tig  = lane & 3;
    const int w    = tid >> 5;
    const int wm   = w >> 1;               // 0..3
    const int wn   = w & 1;                // 0..1
    const int row0 = blockIdx.y * 128;
    const int col0 = blockIdx.x * 128;

    float c[2][8][4];
#pragma unroll
    for (int mt = 0; mt < 2; mt++)
#pragma unroll
        for (int nt = 0; nt < 8; nt++)
#pragma unroll
            for (int j = 0; j < 4; j++) c[mt][nt][j] = 0.f;

    const int xr = tid >> 1, xk = (tid & 1) * 16;   // X fill: row, k-slice
    const int wr = tid >> 3, wc = (tid & 7) * 16;   // W fill: k-row, col-slice

    float4 xs4[4], ws4[4];
    // prologue load of k-tile 0
    {
        const float* xsrc = X + (size_t)(row0 + xr) * DIM + xk;
        const float* wsrc = W + (size_t)wr * TD + col0 + wc;
#pragma unroll
        for (int i = 0; i < 4; i++) { xs4[i] = *(const float4*)(xsrc + 4 * i);
                                      ws4[i] = *(const float4*)(wsrc + 4 * i); }
    }

    for (int k0 = 0; k0 < DIM; k0 += 32) {
        // store staged tile (tf32-rounded)
#pragma unroll
        for (int i = 0; i < 4; i++) {
            *(uint4*)&Xs[xr * XS_STR + xk + 4 * i] =
                make_uint4(tf32u(xs4[i].x), tf32u(xs4[i].y), tf32u(xs4[i].z), tf32u(xs4[i].w));
            *(uint4*)&Ws[wr * WS_STR + wc + 4 * i] =
                make_uint4(tf32u(ws4[i].x), tf32u(ws4[i].y), tf32u(ws4[i].z), tf32u(ws4[i].w));
        }
        __syncthreads();

        // prefetch next k-tile into registers (overlaps compute)
        if (k0 + 32 < DIM) {
            const float* xsrc = X + (size_t)(row0 + xr) * DIM + k0 + 32 + xk;
            const float* wsrc = W + (size_t)(k0 + 32 + wr) * TD + col0 + wc;
#pragma unroll
            for (int i = 0; i < 4; i++) { xs4[i] = *(const float4*)(xsrc + 4 * i);
                                          ws4[i] = *(const float4*)(wsrc + 4 * i); }
        }

#pragma unroll
        for (int kc = 0; kc < 4; kc++) {
            unsigned a[2][4];
#pragma unroll
            for (int mt = 0; mt < 2; mt++) {
                const unsigned* qp = &Xs[(wm * 32 + mt * 16 + gid) * XS_STR + kc * 8 + tig];
                a[mt][0] = qp[0];
                a[mt][2] = qp[4];
                a[mt][1] = qp[8 * XS_STR];
                a[mt][3] = qp[8 * XS_STR + 4];
            }
#pragma unroll
            for (int nt = 0; nt < 8; nt++) {
                unsigned b0 = Ws[(kc * 8 + tig)     * WS_STR + wn * 64 + nt * 8 + gid];
                unsigned b1 = Ws[(kc * 8 + tig + 4) * WS_STR + wn * 64 + nt * 8 + gid];
                mma8(c[0][nt], a[0], b0, b1);
                mma8(c[1][nt], a[1], b0, b1);
            }
        }
        __syncthreads();
    }

    // epilogue: bias + scatter into g_qkv[s][b*NH+h][n][d]
    const size_t per_s = (size_t)B * NH * NSEQ * HD;
#pragma unroll
    for (int mt = 0; mt < 2; mt++) {
        const int r_lo = row0 + wm * 32 + mt * 16 + gid;
        const int r_hi = r_lo + 8;
#pragma unroll
        for (int nt = 0; nt < 8; nt++) {
            const int cA = col0 + wn * 64 + nt * 8 + 2 * tig;
#pragma unroll
            for (int e = 0; e < 2; e++) {
                const int cc = cA + e;
                const float bb = __ldg(&bias[cc]);
                const int s  = cc / DIM;
                const int rem = cc - s * DIM;
                const int h  = rem / HD;
                const int d  = rem - h * HD;
#pragma unroll
                for (int half = 0; half < 2; half++) {
                    const int r = half ? r_hi : r_lo;
                    const int b = r >> 12;
                    const int n = r & 4095;
                    const float v = c[mt][nt][half * 2 + e] + bb;
                    g_qkv[(size_t)s * per_s +
                          (((size_t)(b * NH + h)) * NSEQ + n) * HD + d] = v;
                }
            }
        }
    }
}

// ---------------------------------------------------------------------------
// Kernel 2: flash attention, TF32 mma + cp.async double-buffered K/V.
// grid = (NSEQ/256, B*NH), CTA 512 thr (16 warps), q-tile 256 (16 rows/warp),
// kv-tile 64.  K/V stored RAW f32 (mma reads tf32 bits; RZ truncation).
// smem words: Qs 256*100 | K0 64*100 | K1 64*100 | V0 64*104 | V1 64*104
// ---------------------------------------------------------------------------
#define QT 256
#define QS_STR 100
#define KS_STR 100
#define VS_STR 104
#define KWORDS (64 * KS_STR)          // 6400
#define VWORDS (64 * VS_STR)          // 6656
#define OFF_K  (QT * QS_STR)          // 25600
#define OFF_V  (OFF_K + 2 * KWORDS)   // 38400
#define ATTN_SMEM_WORDS (OFF_V + 2 * VWORDS)
#define ATTN_SMEM_BYTES (ATTN_SMEM_WORDS * 4)

__global__ __launch_bounds__(512, 1) void attn_kernel(
    float* __restrict__ out, int B)
{
    extern __shared__ unsigned asmem[];
    unsigned* Qs = asmem;
    const unsigned smemA = (unsigned)__cvta_generic_to_shared(asmem);

    const int tid  = threadIdx.x;
    const int lane = tid & 31;
    const int gid  = lane >> 2;
    const int tig  = lane & 3;
    const int w    = tid >> 5;                  // 0..15: rows [16w, 16w+16)
    const int bh   = blockIdx.y;
    const int q0   = blockIdx.x * QT;

    const size_t per_s = (size_t)B * NH * NSEQ * HD;
    const float* Qg = g_qkv + (size_t)bh * NSEQ * HD;
    const float* Kg = Qg + per_s;
    const float* Vg = Kg + per_s;

    // ---- precompute cp.async fill mapping (constant across tiles) ----
    // 3072 16B-chunks per tile: [0,1536) -> K rows, [1536,3072) -> V rows
    int      fArr[6];
    unsigned fSoff[6];     // word offset inside the K or V buffer
    unsigned fGoff[6];     // float offset inside the 64x96 global tile
#pragma unroll
    for (int i = 0; i < 6; i++) {
        int c   = tid + i * 512;
        int arr = (c >= 1536);
        int rem = c - (arr ? 1536 : 0);
        int r   = rem / 24;
        int ch  = rem - r * 24;
        fArr[i]  = arr;
        fSoff[i] = arr ? (unsigned)(r * VS_STR + ch * 4) : (unsigned)(r * KS_STR + ch * 4);
        fGoff[i] = (unsigned)(r * HD + ch * 4);
    }

    // ---- issue fills for tile 0 (buf 0) ----
    {
        const unsigned kB = smemA + OFF_K * 4;
        const unsigned vB = smemA + OFF_V * 4;
#pragma unroll
        for (int i = 0; i < 6; i++) {
            const float* src = (fArr[i] ? Vg : Kg) + fGoff[i];
            cp16((fArr[i] ? vB : kB) + fSoff[i] * 4, src);
        }
        cp_commit();
    }

    // ---- load Q tile (tf32-rounded, RNA) ----
    {
        const int row = tid >> 1, dp = (tid & 1) * 48;
        const float* src = Qg + (size_t)(q0 + row) * HD + dp;
#pragma unroll
        for (int i = 0; i < 12; i++) {
            float4 v = *(const float4*)(src + 4 * i);
            *(uint4*)&Qs[row * QS_STR + dp + 4 * i] =
                make_uint4(tf32u(v.x), tf32u(v.y), tf32u(v.z), tf32u(v.w));
        }
    }

    // softmax state + O accumulators
    float m_lo = -INFINITY, m_hi = -INFINITY, l_lo = 0.f, l_hi = 0.f;
    float o[12][4];
#pragma unroll
    for (int nt = 0; nt < 12; nt++)
#pragma unroll
        for (int j = 0; j < 4; j++) o[nt][j] = 0.f;

    // shuffle source lanes for C->A fragment conversion
    const int srcA = (lane & 28) | (tig >> 1);
    const int srcB = srcA + 2;
    const bool oddl = lane & 1;

    const unsigned* qbase = &Qs[(w * 16 + gid) * QS_STR + tig];

    for (int t = 0; t < NSEQ / 64; ++t) {
        const int buf = t & 1;
        cp_wait0();
        __syncthreads();              // tile t resident; prev bufs free

        // issue fills for tile t+1 into the other buffers (overlaps compute)
        if (t + 1 < NSEQ / 64) {
            const int nbuf = buf ^ 1;
            const size_t gbase = (size_t)(t + 1) * 64 * HD;
            const unsigned kB = smemA + (OFF_K + nbuf * KWORDS) * 4;
            const unsigned vB = smemA + (OFF_V + nbuf * VWORDS) * 4;
#pragma unroll
            for (int i = 0; i < 6; i++) {
                const float* src = (fArr[i] ? Vg : Kg) + gbase + fGoff[i];
                cp16((fArr[i] ? vB : kB) + fSoff[i] * 4, src);
            }
            cp_commit();
        }

        const unsigned* Kc = asmem + OFF_K + buf * KWORDS;
        const unsigned* Vc = asmem + OFF_V + buf * VWORDS;

        // ---- S = Q K^T : 12 k-chunks x 8 n-tiles ----
        float s[8][4];
#pragma unroll
        for (int nt = 0; nt < 8; nt++)
#pragma unroll
            for (int j = 0; j < 4; j++) s[nt][j] = 0.f;

#pragma unroll
        for (int kc = 0; kc < 12; kc++) {
            unsigned a[4];
            a[0] = qbase[kc * 8];
            a[2] = qbase[kc * 8 + 4];
            a[1] = qbase[8 * QS_STR + kc * 8];
            a[3] = qbase[8 * QS_STR + kc * 8 + 4];
#pragma unroll
            for (int nt = 0; nt < 8; nt++) {
                const unsigned* kp = &Kc[(nt * 8 + gid) * KS_STR + kc * 8 + tig];
                mma8(s[nt], a, kp[0], kp[4]);
            }
        }

        // ---- online softmax ----
        float rmax_lo = -INFINITY, rmax_hi = -INFINITY;
#pragma unroll
        for (int nt = 0; nt < 8; nt++) {
            rmax_lo = fmaxf(rmax_lo, fmaxf(s[nt][0], s[nt][1]));
            rmax_hi = fmaxf(rmax_hi, fmaxf(s[nt][2], s[nt][3]));
        }
        rmax_lo = fmaxf(rmax_lo, __shfl_xor_sync(0xffffffffu, rmax_lo, 1));
        rmax_lo = fmaxf(rmax_lo, __shfl_xor_sync(0xffffffffu, rmax_lo, 2));
        rmax_hi = fmaxf(rmax_hi, __shfl_xor_sync(0xffffffffu, rmax_hi, 1));
        rmax_hi = fmaxf(rmax_hi, __shfl_xor_sync(0xffffffffu, rmax_hi, 2));

        const float mn_lo = fmaxf(m_lo, rmax_lo * SCALE);
        const float mn_hi = fmaxf(m_hi, rmax_hi * SCALE);
        const float corr_lo = __expf(m_lo - mn_lo);
        const float corr_hi = __expf(m_hi - mn_hi);
        m_lo = mn_lo; m_hi = mn_hi;

        float sum_lo = 0.f, sum_hi = 0.f;
#pragma unroll
        for (int nt = 0; nt < 8; nt++) {
            float e0 = __expf(fmaf(s[nt][0], SCALE, -mn_lo));
            float e1 = __expf(fmaf(s[nt][1], SCALE, -mn_lo));
            float e2 = __expf(fmaf(s[nt][2], SCALE, -mn_hi));
            float e3 = __expf(fmaf(s[nt][3], SCALE, -mn_hi));
            sum_lo += e0 + e1;
            sum_hi += e2 + e3;
            s[nt][0] = __uint_as_float(tf32u(e0));
            s[nt][1] = __uint_as_float(tf32u(e1));
            s[nt][2] = __uint_as_float(tf32u(e2));
            s[nt][3] = __uint_as_float(tf32u(e3));
        }
        sum_lo += __shfl_xor_sync(0xffffffffu, sum_lo, 1);
        sum_lo += __shfl_xor_sync(0xffffffffu, sum_lo, 2);
        sum_hi += __shfl_xor_sync(0xffffffffu, sum_hi, 1);
        sum_hi += __shfl_xor_sync(0xffffffffu, sum_hi, 2);
        l_lo = l_lo * corr_lo + sum_lo;
        l_hi = l_hi * corr_hi + sum_hi;

#pragma unroll
        for (int nt = 0; nt < 12; nt++) {
            o[nt][0] *= corr_lo; o[nt][1] *= corr_lo;
            o[nt][2] *= corr_hi; o[nt][3] *= corr_hi;
        }

        // ---- O += P @ V : 8 k-chunks x 12 d-tiles ----
#pragma unroll
        for (int kc = 0; kc < 8; kc++) {
            float p0 = s[kc][0], p1 = s[kc][1], p2 = s[kc][2], p3 = s[kc][3];
            float t0 = __shfl_sync(0xffffffffu, p0, srcA);
            float t1 = __shfl_sync(0xffffffffu, p1, srcA);
            float t2 = __shfl_sync(0xffffffffu, p2, srcA);
            float t3 = __shfl_sync(0xffffffffu, p3, srcA);
            float u0 = __shfl_sync(0xffffffffu, p0, srcB);
            float u1 = __shfl_sync(0xffffffffu, p1, srcB);
            float u2 = __shfl_sync(0xffffffffu, p2, srcB);
            float u3 = __shfl_sync(0xffffffffu, p3, srcB);
            unsigned a[4];
            a[0] = __float_as_uint(oddl ? t1 : t0);
            a[1] = __float_as_uint(oddl ? t3 : t2);
            a[2] = __float_as_uint(oddl ? u1 : u0);
            a[3] = __float_as_uint(oddl ? u3 : u2);
#pragma unroll
            for (int nt = 0; nt < 12; nt++) {
                const unsigned* vp = &Vc[(kc * 8 + tig) * VS_STR + nt * 8 + gid];
                mma8(o[nt], a, vp[0], vp[4 * VS_STR]);
            }
        }
    }

    // ---- epilogue ----
    const int b = bh >> 3;
    const int h = bh & 7;
    const int r_lo = q0 + w * 16 + gid;
    const int r_hi = r_lo + 8;
    const float inv_lo = 1.f / l_lo;
    const float inv_hi = 1.f / l_hi;
    float* out_lo = out + ((size_t)b * NSEQ + r_lo) * DIM + h * HD;
    float* out_hi = out + ((size_t)b * NSEQ + r_hi) * DIM + h * HD;
#pragma unroll
    for (int nt = 0; nt < 12; nt++) {
        const int d = nt * 8 + 2 * tig;
        *(float2*)&out_lo[d] = make_float2(o[nt][0] * inv_lo, o[nt][1] * inv_lo);
        *(float2*)&out_hi[d] = make_float2(o[nt][2] * inv_hi, o[nt][3] * inv_hi);
    }
}

// ---------------------------------------------------------------------------
extern "C" void kernel_launch(void* const* d_in, const int* in_sizes, int n_in,
                              void* d_out, int out_size)
{
    const float* x    = (const float*)d_in[0];   // (B, N, 768)
    const float* Wqkv = (const float*)d_in[1];   // (768, 2304)
    const float* bqkv = (const float*)d_in[2];   // (2304,)
    float* out = (float*)d_out;

    const int B = in_sizes[0] / (NSEQ * DIM);

    // QKV projection + scatter
    {
        dim3 grid(TD / 128, (B * NSEQ) / 128);
        qkv_gemm_kernel<<<grid, 256>>>(x, Wqkv, bqkv, B);
    }

    // flash attention
    {
        cudaFuncSetAttribute(attn_kernel,
                             cudaFuncAttributeMaxDynamicSharedMemorySize,
                             ATTN_SMEM_BYTES);
        dim3 grid(NSEQ / QT, B * NH);
        attn_kernel<<<grid, 512, ATTN_SMEM_BYTES>>>(out, B);
    }
}